// round 1
// baseline (speedup 1.0000x reference)
#include <cuda_runtime.h>
#include <math.h>
#include <stdint.h>

#define BB 4
#define SS 4096
#define DD 768
#define FFD 3072
#define HH 12
#define HDIM 64
#define WW 128
#define NC (SS / WW)       // 32 chunks
#define ROWS (BB * SS)     // 16384
#define KT 192             // keys per smem tile (2 tiles cover 3*WW = 384 window)

// ---------------------------------------------------------------------------
// Scratch (device globals; no runtime allocation allowed)
// ---------------------------------------------------------------------------
__device__ float g_x[ROWS * DD];
__device__ float g_q[ROWS * DD];
__device__ float g_k[ROWS * DD];
__device__ float g_v[ROWS * DD];
__device__ float g_a[ROWS * DD];
__device__ float g_h[ROWS * FFD];

// ---------------------------------------------------------------------------
// SGEMM: C = ((A @ B) + bias) * alpha, optional ReLU.
// A: MxK row-major, B: KxN row-major, C: MxN row-major.
// M % 128 == 0, N % 128 == 0, K % 8 == 0 (holds for all shapes here).
// ---------------------------------------------------------------------------
__global__ __launch_bounds__(256)
void sgemm_kernel(const float* __restrict__ A, const float* __restrict__ B,
                  const float* __restrict__ bias, float* __restrict__ C,
                  int M, int N, int K, float alpha, int relu)
{
    const int BM = 128, BN = 128, BK = 8, TM = 8, TN = 8;
    __shared__ float As[BK][BM];
    __shared__ float Bs[BK][BN];

    const int bcol = blockIdx.x;   // N tile
    const int brow = blockIdx.y;   // M tile
    const int tid  = threadIdx.x;  // 256

    const int trow = (tid / 16) * TM;
    const int tcol = (tid % 16) * TN;

    const float* Ab = A + (size_t)brow * BM * K;
    const float* Bb = B + bcol * BN;
    float*       Cb = C + (size_t)brow * BM * N + bcol * BN;

    const int aRow = tid / 2;            // 0..127
    const int aCol = (tid % 2) * 4;      // 0 or 4
    const int bRow = tid / 32;           // 0..7
    const int bCol = (tid % 32) * 4;     // 0..124

    float acc[TM][TN];
#pragma unroll
    for (int i = 0; i < TM; i++)
#pragma unroll
        for (int j = 0; j < TN; j++) acc[i][j] = 0.0f;

    float regA[TM], regB[TN];

    for (int k0 = 0; k0 < K; k0 += BK) {
        float4 av = *reinterpret_cast<const float4*>(Ab + (size_t)aRow * K + k0 + aCol);
        As[aCol + 0][aRow] = av.x;
        As[aCol + 1][aRow] = av.y;
        As[aCol + 2][aRow] = av.z;
        As[aCol + 3][aRow] = av.w;
        float4 bv = *reinterpret_cast<const float4*>(Bb + (size_t)(k0 + bRow) * N + bCol);
        *reinterpret_cast<float4*>(&Bs[bRow][bCol]) = bv;
        __syncthreads();

#pragma unroll
        for (int k = 0; k < BK; k++) {
#pragma unroll
            for (int i = 0; i < TM; i++) regA[i] = As[k][trow + i];
#pragma unroll
            for (int j = 0; j < TN; j++) regB[j] = Bs[k][tcol + j];
#pragma unroll
            for (int i = 0; i < TM; i++)
#pragma unroll
                for (int j = 0; j < TN; j++)
                    acc[i][j] = fmaf(regA[i], regB[j], acc[i][j]);
        }
        __syncthreads();
    }

    const int biasBase = bcol * BN + tcol;
#pragma unroll
    for (int i = 0; i < TM; i++) {
#pragma unroll
        for (int j = 0; j < TN; j++) {
            float v = (acc[i][j] + bias[biasBase + j]) * alpha;
            if (relu) v = fmaxf(v, 0.0f);
            Cb[(size_t)(trow + i) * N + tcol + j] = v;
        }
    }
}

// ---------------------------------------------------------------------------
// Sliding-window attention. One CTA per (chunk c, head h, batch b).
// 128 threads = 1 query each. K/V staged in smem in two KT=192 key tiles.
// Online softmax; q and o accumulators in registers.
// ---------------------------------------------------------------------------
__global__ __launch_bounds__(128)
void attn_kernel(const float* __restrict__ q, const float* __restrict__ k,
                 const float* __restrict__ v, float* __restrict__ out)
{
    extern __shared__ float sm[];
    float* ks = sm;             // KT * 64
    float* vs = sm + KT * 64;   // KT * 64

    const int c = blockIdx.x, h = blockIdx.y, b = blockIdx.z;
    const int tid = threadIdx.x;
    const int qi = tid;
    const int qpos = c * WW + qi;
    const size_t base_bh = (size_t)b * SS * DD + (size_t)h * HDIM;

    float qreg[64];
    {
        const float* qp = q + base_bh + (size_t)qpos * DD;
#pragma unroll
        for (int i = 0; i < 16; i++) {
            float4 t = *reinterpret_cast<const float4*>(qp + i * 4);
            qreg[i * 4 + 0] = t.x; qreg[i * 4 + 1] = t.y;
            qreg[i * 4 + 2] = t.z; qreg[i * 4 + 3] = t.w;
        }
    }

    float o[64];
#pragma unroll
    for (int d = 0; d < 64; d++) o[d] = 0.0f;
    float m = -1e30f, l = 0.0f;

    for (int kt = 0; kt < 2; kt++) {
        // Stage K/V tile: window rows [kt*KT, kt*KT+KT) map to kpos = c*WW - WW + row
        for (int idx = tid; idx < KT * 16; idx += 128) {
            int row = idx >> 4;
            int c4  = (idx & 15) << 2;
            int kpos = c * WW - WW + kt * KT + row;
            float4 kv = make_float4(0.f, 0.f, 0.f, 0.f);
            float4 vv = make_float4(0.f, 0.f, 0.f, 0.f);
            if (kpos >= 0 && kpos < SS) {
                size_t off = base_bh + (size_t)kpos * DD + c4;
                kv = *reinterpret_cast<const float4*>(k + off);
                vv = *reinterpret_cast<const float4*>(v + off);
            }
            *reinterpret_cast<float4*>(ks + row * 64 + c4) = kv;
            *reinterpret_cast<float4*>(vs + row * 64 + c4) = vv;
        }
        __syncthreads();

#pragma unroll 1
        for (int j0 = 0; j0 < KT; j0 += 8) {
            float sc[8];
#pragma unroll
            for (int j = 0; j < 8; j++) {
                const float* kr = ks + (j0 + j) * 64;
                float s0 = 0.f, s1 = 0.f, s2 = 0.f, s3 = 0.f;
#pragma unroll
                for (int d = 0; d < 64; d += 4) {
                    s0 = fmaf(qreg[d + 0], kr[d + 0], s0);
                    s1 = fmaf(qreg[d + 1], kr[d + 1], s1);
                    s2 = fmaf(qreg[d + 2], kr[d + 2], s2);
                    s3 = fmaf(qreg[d + 3], kr[d + 3], s3);
                }
                int kjw  = kt * KT + j0 + j;          // index in 3w window
                int kpos = c * WW + kjw - WW;         // global key position
                bool ok = (kjw >= qi) && (kjw <= qi + 2 * WW) &&
                          (kpos >= 0) && (kpos < SS);
                sc[j] = ok ? ((s0 + s1) + (s2 + s3)) : -3.0e38f;
            }
            float mc = sc[0];
#pragma unroll
            for (int j = 1; j < 8; j++) mc = fmaxf(mc, sc[j]);
            float mn = fmaxf(m, mc);
            float scale = __expf(m - mn);
            float p[8];
            float ls = 0.f;
#pragma unroll
            for (int j = 0; j < 8; j++) { p[j] = __expf(sc[j] - mn); ls += p[j]; }
            l = l * scale + ls;
            m = mn;
#pragma unroll
            for (int d = 0; d < 64; d++) o[d] *= scale;
#pragma unroll
            for (int j = 0; j < 8; j++) {
                const float* vr = vs + (j0 + j) * 64;
                float pj = p[j];
#pragma unroll
                for (int d = 0; d < 64; d++) o[d] = fmaf(pj, vr[d], o[d]);
            }
        }
        __syncthreads();
    }

    float inv = 1.0f / l;
    float* op = out + base_bh + (size_t)qpos * DD;
#pragma unroll
    for (int i = 0; i < 16; i++) {
        float4 t;
        t.x = o[i * 4 + 0] * inv; t.y = o[i * 4 + 1] * inv;
        t.z = o[i * 4 + 2] * inv; t.w = o[i * 4 + 3] * inv;
        *reinterpret_cast<float4*>(op + i * 4) = t;
    }
}

// ---------------------------------------------------------------------------
// Residual add + LayerNorm over D=768. One CTA (256 thr) per row.
// out = LN(x + r) * g + beta
// ---------------------------------------------------------------------------
__device__ __forceinline__ float block_sum(float v, float* sh)
{
    __syncthreads();  // protect sh reuse across calls
    int lane = threadIdx.x & 31, w = threadIdx.x >> 5;
#pragma unroll
    for (int o = 16; o; o >>= 1) v += __shfl_xor_sync(0xffffffffu, v, o);
    if (lane == 0) sh[w] = v;
    __syncthreads();
    float t = (lane < 8) ? sh[lane] : 0.0f;
#pragma unroll
    for (int o = 4; o; o >>= 1) t += __shfl_xor_sync(0xffffffffu, t, o);
    if (threadIdx.x == 0) sh[0] = t;
    __syncthreads();
    return sh[0];
}

__global__ __launch_bounds__(256)
void add_ln_kernel(const float* __restrict__ x, const float* __restrict__ r,
                   const float* __restrict__ g, const float* __restrict__ bt,
                   float* __restrict__ out)
{
    __shared__ float sh[8];
    const int row = blockIdx.x;
    const int tid = threadIdx.x;
    const float* xr = x + (size_t)row * DD;
    const float* rr = r + (size_t)row * DD;

    float vals[3];
    float s = 0.f;
#pragma unroll
    for (int i = 0; i < 3; i++) {
        int d = tid + i * 256;
        float v = xr[d] + rr[d];
        vals[i] = v;
        s += v;
    }
    s = block_sum(s, sh);
    float mean = s * (1.0f / (float)DD);
    float vs2 = 0.f;
#pragma unroll
    for (int i = 0; i < 3; i++) {
        float d = vals[i] - mean;
        vs2 += d * d;
    }
    vs2 = block_sum(vs2, sh);
    float inv = rsqrtf(vs2 * (1.0f / (float)DD) + 1e-5f);

    float* orow = out + (size_t)row * DD;
#pragma unroll
    for (int i = 0; i < 3; i++) {
        int d = tid + i * 256;
        orow[d] = (vals[i] - mean) * inv * g[d] + bt[d];
    }
}

// ---------------------------------------------------------------------------
// Host driver
// ---------------------------------------------------------------------------
extern "C" void kernel_launch(void* const* d_in, const int* in_sizes, int n_in,
                              void* d_out, int out_size)
{
    (void)in_sizes; (void)n_in; (void)out_size;

    const float* x0  = (const float*)d_in[0];
    const float* Wq  = (const float*)d_in[1];
    const float* bq  = (const float*)d_in[2];
    const float* Wk  = (const float*)d_in[3];
    const float* bk  = (const float*)d_in[4];
    const float* Wv  = (const float*)d_in[5];
    const float* bv  = (const float*)d_in[6];
    const float* W1  = (const float*)d_in[7];
    const float* b1  = (const float*)d_in[8];
    const float* W2  = (const float*)d_in[9];
    const float* b2  = (const float*)d_in[10];
    const float* g1  = (const float*)d_in[11];
    const float* be1 = (const float*)d_in[12];
    const float* g2  = (const float*)d_in[13];
    const float* be2 = (const float*)d_in[14];
    // d_in[15] = n_heads, d_in[16] = window (compile-time constants here)

    float* outp = (float*)d_out;

    float *qb, *kb, *vb, *ab, *hb, *xb;
    cudaGetSymbolAddress((void**)&qb, g_q);
    cudaGetSymbolAddress((void**)&kb, g_k);
    cudaGetSymbolAddress((void**)&vb, g_v);
    cudaGetSymbolAddress((void**)&ab, g_a);
    cudaGetSymbolAddress((void**)&hb, g_h);
    cudaGetSymbolAddress((void**)&xb, g_x);

    const int attn_smem = 2 * KT * 64 * (int)sizeof(float);  // 96 KB
    cudaFuncSetAttribute(attn_kernel, cudaFuncAttributeMaxDynamicSharedMemorySize,
                         attn_smem);

    dim3 gD(DD / 128, ROWS / 128);    // (6, 128)
    dim3 gF(FFD / 128, ROWS / 128);   // (24, 128)
    dim3 gA(NC, HH, BB);              // (32, 12, 4)

    const float* xc = x0;
    for (int l = 0; l < 4; l++) {
        const size_t wOff  = (size_t)l * DD * DD;
        const size_t w1Off = (size_t)l * DD * FFD;
        const size_t w2Off = (size_t)l * FFD * DD;

        // QKV projections (q pre-scaled by 1/sqrt(hd) = 0.125)
        sgemm_kernel<<<gD, 256>>>(xc, Wq + wOff, bq + l * DD, qb,
                                  ROWS, DD, DD, 0.125f, 0);
        sgemm_kernel<<<gD, 256>>>(xc, Wk + wOff, bk + l * DD, kb,
                                  ROWS, DD, DD, 1.0f, 0);
        sgemm_kernel<<<gD, 256>>>(xc, Wv + wOff, bv + l * DD, vb,
                                  ROWS, DD, DD, 1.0f, 0);

        attn_kernel<<<gA, 128, attn_smem>>>(qb, kb, vb, ab);

        add_ln_kernel<<<ROWS, 256>>>(xc, ab, g1 + l * DD, be1 + l * DD, xb);

        sgemm_kernel<<<gF, 256>>>(xb, W1 + w1Off, b1 + l * FFD, hb,
                                  ROWS, FFD, DD, 1.0f, 1);
        sgemm_kernel<<<gD, 256>>>(hb, W2 + w2Off, b2 + l * DD, ab,
                                  ROWS, DD, FFD, 1.0f, 0);

        float* xdst = (l == 3) ? outp : xb;
        add_ln_kernel<<<ROWS, 256>>>(xb, ab, g2 + l * DD, be2 + l * DD, xdst);

        xc = xb;
    }
}

// round 3
// speedup vs baseline: 2.4197x; 2.4197x over previous
#include <cuda_runtime.h>
#include <math.h>
#include <stdint.h>

#define BB 4
#define SS 4096
#define DD 768
#define FFD 3072
#define HH 12
#define WW 128
#define NC (SS / WW)
#define ROWS (BB * SS)
#define KT 192

#define BM 128
#define BN 128
#define BK 16
#define STAGES 4
#define TSTRIDE 20                 // padded floats per smem row (conflict-free)
#define STAGE_FLOATS (128 * TSTRIDE)

// ---------------------------------------------------------------------------
// Scratch (device globals; no runtime allocation allowed)
// ---------------------------------------------------------------------------
__device__ float g_x[ROWS * DD];
__device__ float g_q[ROWS * DD];
__device__ float g_k[ROWS * DD];
__device__ float g_v[ROWS * DD];
__device__ float g_a[ROWS * DD];
__device__ float g_h[(size_t)ROWS * FFD];
__device__ float g_WqT[4 * DD * DD];
__device__ float g_WkT[4 * DD * DD];
__device__ float g_WvT[4 * DD * DD];
__device__ float g_W1T[4 * DD * FFD];
__device__ float g_W2T[4 * DD * FFD];

// ---------------------------------------------------------------------------
// Helpers (family-portable PTX only: cp.async + mma.sync, no tcgen05/TMA)
// ---------------------------------------------------------------------------
__device__ __forceinline__ uint32_t smem_u32(const void* p) {
    uint32_t a;
    asm("{ .reg .u64 t; cvta.to.shared.u64 t, %1; cvt.u32.u64 %0, t; }"
        : "=r"(a) : "l"(p));
    return a;
}
__device__ __forceinline__ float to_tf32(float x) {
    uint32_t u;
    asm("cvt.rn.tf32.f32 %0, %1;" : "=r"(u) : "f"(x));
    return __uint_as_float(u);
}
__device__ __forceinline__ uint32_t to_tf32_u(float x) {
    uint32_t u;
    asm("cvt.rn.tf32.f32 %0, %1;" : "=r"(u) : "f"(x));
    return u;
}
__device__ __forceinline__ void cp_async16(uint32_t dst, const void* src) {
    asm volatile("cp.async.cg.shared.global [%0], [%1], 16;"
                 :: "r"(dst), "l"(src));
}
__device__ __forceinline__ void cp_commit() {
    asm volatile("cp.async.commit_group;" ::: "memory");
}
template <int N>
__device__ __forceinline__ void cp_wait() {
    asm volatile("cp.async.wait_group %0;" :: "n"(N) : "memory");
}

__device__ __forceinline__ void mma_tf32(float* c, const uint32_t* a,
                                         const uint32_t* b) {
    asm volatile(
        "mma.sync.aligned.m16n8k8.row.col.f32.tf32.tf32.f32 "
        "{%0,%1,%2,%3}, {%4,%5,%6,%7}, {%8,%9}, {%0,%1,%2,%3};"
        : "+f"(c[0]), "+f"(c[1]), "+f"(c[2]), "+f"(c[3])
        : "r"(a[0]), "r"(a[1]), "r"(a[2]), "r"(a[3]), "r"(b[0]), "r"(b[1]));
}

// ---------------------------------------------------------------------------
// Weight transpose: src [L, K, N] -> dst [L, N, K], with tf32 RN rounding.
// ---------------------------------------------------------------------------
__global__ __launch_bounds__(256)
void transpose_w(const float* __restrict__ src, float* __restrict__ dst,
                 int K, int N)
{
    __shared__ float t[32][33];
    const int l = blockIdx.z;
    src += (size_t)l * K * N;
    dst += (size_t)l * K * N;
    const int kb = blockIdx.y * 32, nb = blockIdx.x * 32;
    const int tx = threadIdx.x, ty = threadIdx.y;  // 32 x 8
#pragma unroll
    for (int i = 0; i < 32; i += 8)
        t[ty + i][tx] = src[(size_t)(kb + ty + i) * N + nb + tx];
    __syncthreads();
#pragma unroll
    for (int i = 0; i < 32; i += 8)
        dst[(size_t)(nb + ty + i) * K + kb + tx] = to_tf32(t[tx][ty + i]);
}

// ---------------------------------------------------------------------------
// tf32 mma.sync GEMM: C = ((A @ W) + bias) * alpha, optional ReLU.
// A: [M,K] row-major fp32. BT = W^T: [N,K] row-major (tf32-rounded).
// 128x128 tile, BK=16, 4-stage cp.async pipeline, 8 warps (warp tile 32x64).
// ---------------------------------------------------------------------------
__global__ __launch_bounds__(256)
void gemm_tf32(const float* __restrict__ A, const float* __restrict__ BT,
               const float* __restrict__ bias, float* __restrict__ C,
               int M, int N, int K, float alpha, int relu)
{
    extern __shared__ float sm[];
    float* As = sm;                          // STAGES * STAGE_FLOATS
    float* Bs = sm + STAGES * STAGE_FLOATS;  // STAGES * STAGE_FLOATS

    const int tid = threadIdx.x;
    const int wid = tid >> 5, lane = tid & 31;
    const int warp_m = wid >> 1;     // 0..3  (rows: warp_m*32)
    const int warp_n = wid & 1;      // 0..1  (cols: warp_n*64)
    const int g = lane >> 2;         // 0..7
    const int t4 = lane & 3;         // 0..3

    const int brow = blockIdx.y, bcol = blockIdx.x;
    const float* Abase = A + (size_t)brow * BM * K;
    const float* Bbase = BT + (size_t)bcol * BN * K;

    const uint32_t AsU = smem_u32(As);
    const uint32_t BsU = smem_u32(Bs);

    // staging: 512 float4 per tile, 2 per thread
    const int srow = tid >> 2;          // 0..63  (+64 for second chunk? no:)
    // id scheme: id = tid + i*256, row = id>>2 (0..127), c4 = id&3 (0..3)

    const int nk = K / BK;

    auto stage = [&](int s) {
        const int k0 = s * BK;
        const uint32_t aoff = (uint32_t)((s % STAGES) * STAGE_FLOATS) * 4u;
        const uint32_t boff = aoff;
#pragma unroll
        for (int i = 0; i < 2; i++) {
            int id = tid + i * 256;
            int r = id >> 2, c4 = id & 3;
            cp_async16(AsU + aoff + (uint32_t)(r * TSTRIDE + c4 * 4) * 4u,
                       Abase + (size_t)r * K + k0 + c4 * 4);
        }
#pragma unroll
        for (int i = 0; i < 2; i++) {
            int id = tid + i * 256;
            int r = id >> 2, c4 = id & 3;
            cp_async16(BsU + boff + (uint32_t)(r * TSTRIDE + c4 * 4) * 4u,
                       Bbase + (size_t)r * K + k0 + c4 * 4);
        }
        cp_commit();
    };

    float acc[2][8][4];
#pragma unroll
    for (int mt = 0; mt < 2; mt++)
#pragma unroll
        for (int nt = 0; nt < 8; nt++)
#pragma unroll
            for (int j = 0; j < 4; j++) acc[mt][nt][j] = 0.0f;

    // prologue: stages 0..STAGES-2
#pragma unroll
    for (int s = 0; s < STAGES - 1; s++) {
        if (s < nk) stage(s); else cp_commit();
    }

    for (int ks = 0; ks < nk; ks++) {
        cp_wait<STAGES - 2>();
        __syncthreads();

        // prefetch next
        if (ks + STAGES - 1 < nk) stage(ks + STAGES - 1); else cp_commit();

        const float* Abuf = As + (ks % STAGES) * STAGE_FLOATS;
        const float* Bbuf = Bs + (ks % STAGES) * STAGE_FLOATS;

#pragma unroll
        for (int kk = 0; kk < 2; kk++) {
            const int kx = kk * 8 + t4;
            uint32_t a[2][4];
#pragma unroll
            for (int mt = 0; mt < 2; mt++) {
                const int r = warp_m * 32 + mt * 16 + g;
                a[mt][0] = to_tf32_u(Abuf[r * TSTRIDE + kx]);
                a[mt][1] = to_tf32_u(Abuf[(r + 8) * TSTRIDE + kx]);
                a[mt][2] = to_tf32_u(Abuf[r * TSTRIDE + kx + 4]);
                a[mt][3] = to_tf32_u(Abuf[(r + 8) * TSTRIDE + kx + 4]);
            }
            uint32_t b[8][2];
#pragma unroll
            for (int nt = 0; nt < 8; nt++) {
                const int n = warp_n * 64 + nt * 8 + g;
                b[nt][0] = __float_as_uint(Bbuf[n * TSTRIDE + kx]);
                b[nt][1] = __float_as_uint(Bbuf[n * TSTRIDE + kx + 4]);
            }
#pragma unroll
            for (int mt = 0; mt < 2; mt++)
#pragma unroll
                for (int nt = 0; nt < 8; nt++)
                    mma_tf32(acc[mt][nt], a[mt], b[nt]);
        }
        __syncthreads();
    }

    // epilogue
#pragma unroll
    for (int mt = 0; mt < 2; mt++) {
        const int r0 = brow * BM + warp_m * 32 + mt * 16 + g;
#pragma unroll
        for (int nt = 0; nt < 8; nt++) {
            const int cb = bcol * BN + warp_n * 64 + nt * 8 + t4 * 2;
            const float b0 = bias[cb], b1 = bias[cb + 1];
            float v0 = (acc[mt][nt][0] + b0) * alpha;
            float v1 = (acc[mt][nt][1] + b1) * alpha;
            float v2 = (acc[mt][nt][2] + b0) * alpha;
            float v3 = (acc[mt][nt][3] + b1) * alpha;
            if (relu) {
                v0 = fmaxf(v0, 0.f); v1 = fmaxf(v1, 0.f);
                v2 = fmaxf(v2, 0.f); v3 = fmaxf(v3, 0.f);
            }
            *reinterpret_cast<float2*>(C + (size_t)r0 * N + cb) =
                make_float2(v0, v1);
            *reinterpret_cast<float2*>(C + (size_t)(r0 + 8) * N + cb) =
                make_float2(v2, v3);
        }
    }
}

// ---------------------------------------------------------------------------
// Sliding-window attention (unchanged — works, ~750us/layer).
// ---------------------------------------------------------------------------
__global__ __launch_bounds__(128)
void attn_kernel(const float* __restrict__ q, const float* __restrict__ k,
                 const float* __restrict__ v, float* __restrict__ out)
{
    extern __shared__ float sma[];
    float* ks = sma;
    float* vs = sma + KT * 64;

    const int c = blockIdx.x, h = blockIdx.y, b = blockIdx.z;
    const int tid = threadIdx.x;
    const int qi = tid;
    const int qpos = c * WW + qi;
    const size_t base_bh = (size_t)b * SS * DD + (size_t)h * 64;

    float qreg[64];
    {
        const float* qp = q + base_bh + (size_t)qpos * DD;
#pragma unroll
        for (int i = 0; i < 16; i++) {
            float4 t = *reinterpret_cast<const float4*>(qp + i * 4);
            qreg[i * 4 + 0] = t.x; qreg[i * 4 + 1] = t.y;
            qreg[i * 4 + 2] = t.z; qreg[i * 4 + 3] = t.w;
        }
    }

    float o[64];
#pragma unroll
    for (int d = 0; d < 64; d++) o[d] = 0.0f;
    float m = -1e30f, l = 0.0f;

    for (int kt = 0; kt < 2; kt++) {
        for (int idx = tid; idx < KT * 16; idx += 128) {
            int row = idx >> 4;
            int c4  = (idx & 15) << 2;
            int kpos = c * WW - WW + kt * KT + row;
            float4 kv = make_float4(0.f, 0.f, 0.f, 0.f);
            float4 vv = make_float4(0.f, 0.f, 0.f, 0.f);
            if (kpos >= 0 && kpos < SS) {
                size_t off = base_bh + (size_t)kpos * DD + c4;
                kv = *reinterpret_cast<const float4*>(k + off);
                vv = *reinterpret_cast<const float4*>(v + off);
            }
            *reinterpret_cast<float4*>(ks + row * 64 + c4) = kv;
            *reinterpret_cast<float4*>(vs + row * 64 + c4) = vv;
        }
        __syncthreads();

#pragma unroll 1
        for (int j0 = 0; j0 < KT; j0 += 8) {
            float sc[8];
#pragma unroll
            for (int j = 0; j < 8; j++) {
                const float* kr = ks + (j0 + j) * 64;
                float s0 = 0.f, s1 = 0.f, s2 = 0.f, s3 = 0.f;
#pragma unroll
                for (int d = 0; d < 64; d += 4) {
                    s0 = fmaf(qreg[d + 0], kr[d + 0], s0);
                    s1 = fmaf(qreg[d + 1], kr[d + 1], s1);
                    s2 = fmaf(qreg[d + 2], kr[d + 2], s2);
                    s3 = fmaf(qreg[d + 3], kr[d + 3], s3);
                }
                int kjw  = kt * KT + j0 + j;
                int kpos = c * WW + kjw - WW;
                bool ok = (kjw >= qi) && (kjw <= qi + 2 * WW) &&
                          (kpos >= 0) && (kpos < SS);
                sc[j] = ok ? ((s0 + s1) + (s2 + s3)) : -3.0e38f;
            }
            float mc = sc[0];
#pragma unroll
            for (int j = 1; j < 8; j++) mc = fmaxf(mc, sc[j]);
            float mn = fmaxf(m, mc);
            float scale = __expf(m - mn);
            float p[8];
            float ls = 0.f;
#pragma unroll
            for (int j = 0; j < 8; j++) { p[j] = __expf(sc[j] - mn); ls += p[j]; }
            l = l * scale + ls;
            m = mn;
#pragma unroll
            for (int d = 0; d < 64; d++) o[d] *= scale;
#pragma unroll
            for (int j = 0; j < 8; j++) {
                const float* vr = vs + (j0 + j) * 64;
                float pj = p[j];
#pragma unroll
                for (int d = 0; d < 64; d++) o[d] = fmaf(pj, vr[d], o[d]);
            }
        }
        __syncthreads();
    }

    float inv = 1.0f / l;
    float* op = out + base_bh + (size_t)qpos * DD;
#pragma unroll
    for (int i = 0; i < 16; i++) {
        float4 t;
        t.x = o[i * 4 + 0] * inv; t.y = o[i * 4 + 1] * inv;
        t.z = o[i * 4 + 2] * inv; t.w = o[i * 4 + 3] * inv;
        *reinterpret_cast<float4*>(op + i * 4) = t;
    }
}

// ---------------------------------------------------------------------------
// Residual add + LayerNorm (unchanged).
// ---------------------------------------------------------------------------
__device__ __forceinline__ float block_sum(float v, float* sh)
{
    __syncthreads();
    int lane = threadIdx.x & 31, w = threadIdx.x >> 5;
#pragma unroll
    for (int o = 16; o; o >>= 1) v += __shfl_xor_sync(0xffffffffu, v, o);
    if (lane == 0) sh[w] = v;
    __syncthreads();
    float t = (lane < 8) ? sh[lane] : 0.0f;
#pragma unroll
    for (int o = 4; o; o >>= 1) t += __shfl_xor_sync(0xffffffffu, t, o);
    if (threadIdx.x == 0) sh[0] = t;
    __syncthreads();
    return sh[0];
}

__global__ __launch_bounds__(256)
void add_ln_kernel(const float* __restrict__ x, const float* __restrict__ r,
                   const float* __restrict__ g, const float* __restrict__ bt,
                   float* __restrict__ out)
{
    __shared__ float sh[8];
    const int row = blockIdx.x;
    const int tid = threadIdx.x;
    const float* xr = x + (size_t)row * DD;
    const float* rr = r + (size_t)row * DD;

    float vals[3];
    float s = 0.f;
#pragma unroll
    for (int i = 0; i < 3; i++) {
        int d = tid + i * 256;
        float v = xr[d] + rr[d];
        vals[i] = v;
        s += v;
    }
    s = block_sum(s, sh);
    float mean = s * (1.0f / (float)DD);
    float vs2 = 0.f;
#pragma unroll
    for (int i = 0; i < 3; i++) {
        float d = vals[i] - mean;
        vs2 += d * d;
    }
    vs2 = block_sum(vs2, sh);
    float inv = rsqrtf(vs2 * (1.0f / (float)DD) + 1e-5f);

    float* orow = out + (size_t)row * DD;
#pragma unroll
    for (int i = 0; i < 3; i++) {
        int d = tid + i * 256;
        orow[d] = (vals[i] - mean) * inv * g[d] + bt[d];
    }
}

// ---------------------------------------------------------------------------
// Host driver
// ---------------------------------------------------------------------------
extern "C" void kernel_launch(void* const* d_in, const int* in_sizes, int n_in,
                              void* d_out, int out_size)
{
    (void)in_sizes; (void)n_in; (void)out_size;

    const float* x0  = (const float*)d_in[0];
    const float* Wq  = (const float*)d_in[1];
    const float* bq  = (const float*)d_in[2];
    const float* Wk  = (const float*)d_in[3];
    const float* bk  = (const float*)d_in[4];
    const float* Wv  = (const float*)d_in[5];
    const float* bv  = (const float*)d_in[6];
    const float* W1  = (const float*)d_in[7];
    const float* b1  = (const float*)d_in[8];
    const float* W2  = (const float*)d_in[9];
    const float* b2  = (const float*)d_in[10];
    const float* g1  = (const float*)d_in[11];
    const float* be1 = (const float*)d_in[12];
    const float* g2  = (const float*)d_in[13];
    const float* be2 = (const float*)d_in[14];

    float* outp = (float*)d_out;

    float *qb, *kb, *vb, *ab, *hb, *xb;
    float *wqt, *wkt, *wvt, *w1t, *w2t;
    cudaGetSymbolAddress((void**)&qb, g_q);
    cudaGetSymbolAddress((void**)&kb, g_k);
    cudaGetSymbolAddress((void**)&vb, g_v);
    cudaGetSymbolAddress((void**)&ab, g_a);
    cudaGetSymbolAddress((void**)&hb, g_h);
    cudaGetSymbolAddress((void**)&xb, g_x);
    cudaGetSymbolAddress((void**)&wqt, g_WqT);
    cudaGetSymbolAddress((void**)&wkt, g_WkT);
    cudaGetSymbolAddress((void**)&wvt, g_WvT);
    cudaGetSymbolAddress((void**)&w1t, g_W1T);
    cudaGetSymbolAddress((void**)&w2t, g_W2T);

    const int attn_smem = 2 * KT * 64 * (int)sizeof(float);  // 96 KB
    cudaFuncSetAttribute(attn_kernel, cudaFuncAttributeMaxDynamicSharedMemorySize,
                         attn_smem);
    const int gemm_smem = 2 * STAGES * STAGE_FLOATS * (int)sizeof(float); // 80 KB
    cudaFuncSetAttribute(gemm_tf32, cudaFuncAttributeMaxDynamicSharedMemorySize,
                         gemm_smem);

    // Weight transposes (+ tf32 RN rounding), once per replay.
    dim3 tb(32, 8);
    transpose_w<<<dim3(DD / 32, DD / 32, 4), tb>>>(Wq, wqt, DD, DD);
    transpose_w<<<dim3(DD / 32, DD / 32, 4), tb>>>(Wk, wkt, DD, DD);
    transpose_w<<<dim3(DD / 32, DD / 32, 4), tb>>>(Wv, wvt, DD, DD);
    transpose_w<<<dim3(FFD / 32, DD / 32, 4), tb>>>(W1, w1t, DD, FFD);
    transpose_w<<<dim3(DD / 32, FFD / 32, 4), tb>>>(W2, w2t, FFD, DD);

    dim3 gD(DD / BN, ROWS / BM);     // (6, 128)
    dim3 gF(FFD / BN, ROWS / BM);    // (24, 128)
    dim3 gA(NC, HH, BB);

    const float* xc = x0;
    for (int l = 0; l < 4; l++) {
        const size_t wOff  = (size_t)l * DD * DD;
        const size_t wfOff = (size_t)l * DD * FFD;

        gemm_tf32<<<gD, 256, gemm_smem>>>(xc, wqt + wOff, bq + l * DD, qb,
                                          ROWS, DD, DD, 0.125f, 0);
        gemm_tf32<<<gD, 256, gemm_smem>>>(xc, wkt + wOff, bk + l * DD, kb,
                                          ROWS, DD, DD, 1.0f, 0);
        gemm_tf32<<<gD, 256, gemm_smem>>>(xc, wvt + wOff, bv + l * DD, vb,
                                          ROWS, DD, DD, 1.0f, 0);

        attn_kernel<<<gA, 128, attn_smem>>>(qb, kb, vb, ab);

        add_ln_kernel<<<ROWS, 256>>>(xc, ab, g1 + l * DD, be1 + l * DD, xb);

        gemm_tf32<<<gF, 256, gemm_smem>>>(xb, w1t + wfOff, b1 + l * FFD, hb,
                                          ROWS, FFD, DD, 1.0f, 1);
        gemm_tf32<<<gD, 256, gemm_smem>>>(hb, w2t + wfOff, b2 + l * DD, ab,
                                          ROWS, DD, FFD, 1.0f, 0);

        float* xdst = (l == 3) ? outp : xb;
        add_ln_kernel<<<ROWS, 256>>>(xb, ab, g2 + l * DD, be2 + l * DD, xdst);

        xc = xb;
    }
}

// round 4
// speedup vs baseline: 2.8704x; 1.1862x over previous
#include <cuda_runtime.h>
#include <cuda_fp16.h>
#include <math.h>
#include <stdint.h>

#define BB 4
#define SS 4096
#define DD 768
#define FFD 3072
#define HH 12
#define WW 128
#define NC (SS / WW)
#define ROWS (BB * SS)
#define KT 192

#define GBM 128
#define GBN 128
#define GBK 32
#define GSTAGES 3
#define HSTRIDE 72                    // halves per smem row (padded, conflict-free)
#define HSTAGE (128 * HSTRIDE)        // halves per tile per stage

// ---------------------------------------------------------------------------
// Scratch (device globals; no runtime allocation allowed)
// ---------------------------------------------------------------------------
__device__ float g_x[ROWS * DD];      // running x (fp32)
__device__ float g_xb[ROWS * DD];     // post-LN1 x (fp32)
__device__ float g_q[ROWS * DD];
__device__ float g_k[ROWS * DD];
__device__ float g_v[ROWS * DD];
__device__ float g_a[ROWS * DD];      // attn out / FF2 out
__device__ __half g_xin16[ROWS * DD];   // fp16 twin of layer input
__device__ __half g_xb16[ROWS * DD];    // fp16 twin of post-LN1 x
__device__ __half g_h16[(size_t)ROWS * FFD];  // FF hidden (fp16 only)
__device__ __half g_WqT[4 * DD * DD];
__device__ __half g_WkT[4 * DD * DD];
__device__ __half g_WvT[4 * DD * DD];
__device__ __half g_W1T[4 * DD * FFD];
__device__ __half g_W2T[4 * DD * FFD];

// ---------------------------------------------------------------------------
// Helpers (family-portable PTX only: cp.async + mma.sync)
// ---------------------------------------------------------------------------
__device__ __forceinline__ uint32_t smem_u32(const void* p) {
    uint32_t a;
    asm("{ .reg .u64 t; cvta.to.shared.u64 t, %1; cvt.u32.u64 %0, t; }"
        : "=r"(a) : "l"(p));
    return a;
}
__device__ __forceinline__ void cp_async16(uint32_t dst, const void* src) {
    asm volatile("cp.async.cg.shared.global [%0], [%1], 16;"
                 :: "r"(dst), "l"(src));
}
__device__ __forceinline__ void cp_commit() {
    asm volatile("cp.async.commit_group;" ::: "memory");
}
template <int N>
__device__ __forceinline__ void cp_wait() {
    asm volatile("cp.async.wait_group %0;" :: "n"(N) : "memory");
}
__device__ __forceinline__ void mma_f16(float* c, const uint32_t* a,
                                        const uint32_t* b) {
    asm volatile(
        "mma.sync.aligned.m16n8k16.row.col.f32.f16.f16.f32 "
        "{%0,%1,%2,%3}, {%4,%5,%6,%7}, {%8,%9}, {%0,%1,%2,%3};"
        : "+f"(c[0]), "+f"(c[1]), "+f"(c[2]), "+f"(c[3])
        : "r"(a[0]), "r"(a[1]), "r"(a[2]), "r"(a[3]), "r"(b[0]), "r"(b[1]));
}

// ---------------------------------------------------------------------------
// Weight transpose: src [L, K, N] fp32 -> dst [L, N, K] fp16.
// ---------------------------------------------------------------------------
__global__ __launch_bounds__(256)
void transpose_w(const float* __restrict__ src, __half* __restrict__ dst,
                 int K, int N)
{
    __shared__ float t[32][33];
    const int l = blockIdx.z;
    src += (size_t)l * K * N;
    dst += (size_t)l * K * N;
    const int kb = blockIdx.y * 32, nb = blockIdx.x * 32;
    const int tx = threadIdx.x, ty = threadIdx.y;  // 32 x 8
#pragma unroll
    for (int i = 0; i < 32; i += 8)
        t[ty + i][tx] = src[(size_t)(kb + ty + i) * N + nb + tx];
    __syncthreads();
#pragma unroll
    for (int i = 0; i < 32; i += 8)
        dst[(size_t)(nb + ty + i) * K + kb + tx] = __float2half_rn(t[tx][ty + i]);
}

// fp32 -> fp16 convert (for initial x)
__global__ __launch_bounds__(256)
void f2h_kernel(const float* __restrict__ src, __half* __restrict__ dst, int n)
{
    int i = (blockIdx.x * 256 + threadIdx.x) * 4;
    if (i < n) {
        float4 v = *reinterpret_cast<const float4*>(src + i);
        __half2 h0 = __floats2half2_rn(v.x, v.y);
        __half2 h1 = __floats2half2_rn(v.z, v.w);
        *reinterpret_cast<__half2*>(dst + i) = h0;
        *reinterpret_cast<__half2*>(dst + i + 2) = h1;
    }
}

// ---------------------------------------------------------------------------
// fp16 mma.sync GEMM: out = ((A @ W) + bias) * alpha, optional ReLU.
// A: [M,K] fp16 row-major. BT = W^T: [N,K] fp16 row-major.
// 128x128 tile, BK=32 (2 x k16), 3-stage cp.async, 8 warps (warp tile 32x64).
// Cf (fp32 out) and/or Ch (fp16 out) may be null.
// ---------------------------------------------------------------------------
__global__ __launch_bounds__(256, 2)
void gemm_f16(const __half* __restrict__ A, const __half* __restrict__ BT,
              const float* __restrict__ bias, float* __restrict__ Cf,
              __half* __restrict__ Ch,
              int M, int N, int K, float alpha, int relu)
{
    extern __shared__ __half hsm[];
    __half* As = hsm;                           // GSTAGES * HSTAGE
    __half* Bs = hsm + GSTAGES * HSTAGE;

    const int tid = threadIdx.x;
    const int wid = tid >> 5, lane = tid & 31;
    const int warp_m = wid >> 1;     // 0..3
    const int warp_n = wid & 1;      // 0..1
    const int g = lane >> 2;         // 0..7
    const int t4 = lane & 3;         // 0..3

    const int brow = blockIdx.y, bcol = blockIdx.x;
    const __half* Abase = A + (size_t)brow * GBM * K;
    const __half* Bbase = BT + (size_t)bcol * GBN * K;

    const uint32_t AsU = smem_u32(As);
    const uint32_t BsU = smem_u32(Bs);

    const int nk = K / GBK;

    auto stage = [&](int s) {
        const int k0 = s * GBK;
        const uint32_t off = (uint32_t)((s % GSTAGES) * HSTAGE) * 2u;
#pragma unroll
        for (int i = 0; i < 2; i++) {
            int id = tid + i * 256;
            int r = id >> 2, c4 = id & 3;
            cp_async16(AsU + off + (uint32_t)(r * HSTRIDE + c4 * 8) * 2u,
                       Abase + (size_t)r * K + k0 + c4 * 8);
        }
#pragma unroll
        for (int i = 0; i < 2; i++) {
            int id = tid + i * 256;
            int r = id >> 2, c4 = id & 3;
            cp_async16(BsU + off + (uint32_t)(r * HSTRIDE + c4 * 8) * 2u,
                       Bbase + (size_t)r * K + k0 + c4 * 8);
        }
        cp_commit();
    };

    float acc[2][8][4];
#pragma unroll
    for (int mt = 0; mt < 2; mt++)
#pragma unroll
        for (int nt = 0; nt < 8; nt++)
#pragma unroll
            for (int j = 0; j < 4; j++) acc[mt][nt][j] = 0.0f;

#pragma unroll
    for (int s = 0; s < GSTAGES - 1; s++) {
        if (s < nk) stage(s); else cp_commit();
    }

    for (int ks = 0; ks < nk; ks++) {
        cp_wait<GSTAGES - 2>();
        __syncthreads();

        if (ks + GSTAGES - 1 < nk) stage(ks + GSTAGES - 1); else cp_commit();

        const __half* Abuf = As + (ks % GSTAGES) * HSTAGE;
        const __half* Bbuf = Bs + (ks % GSTAGES) * HSTAGE;

#pragma unroll
        for (int kk = 0; kk < 2; kk++) {
            const int kx = kk * 16 + t4 * 2;
            uint32_t a[2][4];
#pragma unroll
            for (int mt = 0; mt < 2; mt++) {
                const int r = warp_m * 32 + mt * 16 + g;
                a[mt][0] = *reinterpret_cast<const uint32_t*>(&Abuf[r * HSTRIDE + kx]);
                a[mt][1] = *reinterpret_cast<const uint32_t*>(&Abuf[(r + 8) * HSTRIDE + kx]);
                a[mt][2] = *reinterpret_cast<const uint32_t*>(&Abuf[r * HSTRIDE + kx + 8]);
                a[mt][3] = *reinterpret_cast<const uint32_t*>(&Abuf[(r + 8) * HSTRIDE + kx + 8]);
            }
            uint32_t b[8][2];
#pragma unroll
            for (int nt = 0; nt < 8; nt++) {
                const int n = warp_n * 64 + nt * 8 + g;
                b[nt][0] = *reinterpret_cast<const uint32_t*>(&Bbuf[n * HSTRIDE + kx]);
                b[nt][1] = *reinterpret_cast<const uint32_t*>(&Bbuf[n * HSTRIDE + kx + 8]);
            }
#pragma unroll
            for (int mt = 0; mt < 2; mt++)
#pragma unroll
                for (int nt = 0; nt < 8; nt++)
                    mma_f16(acc[mt][nt], a[mt], b[nt]);
        }
        __syncthreads();
    }

    // epilogue
#pragma unroll
    for (int mt = 0; mt < 2; mt++) {
        const int r0 = brow * GBM + warp_m * 32 + mt * 16 + g;
#pragma unroll
        for (int nt = 0; nt < 8; nt++) {
            const int cb = bcol * GBN + warp_n * 64 + nt * 8 + t4 * 2;
            const float b0 = bias[cb], b1 = bias[cb + 1];
            float v0 = (acc[mt][nt][0] + b0) * alpha;
            float v1 = (acc[mt][nt][1] + b1) * alpha;
            float v2 = (acc[mt][nt][2] + b0) * alpha;
            float v3 = (acc[mt][nt][3] + b1) * alpha;
            if (relu) {
                v0 = fmaxf(v0, 0.f); v1 = fmaxf(v1, 0.f);
                v2 = fmaxf(v2, 0.f); v3 = fmaxf(v3, 0.f);
            }
            if (Cf) {
                *reinterpret_cast<float2*>(Cf + (size_t)r0 * N + cb) =
                    make_float2(v0, v1);
                *reinterpret_cast<float2*>(Cf + (size_t)(r0 + 8) * N + cb) =
                    make_float2(v2, v3);
            }
            if (Ch) {
                *reinterpret_cast<__half2*>(Ch + (size_t)r0 * N + cb) =
                    __floats2half2_rn(v0, v1);
                *reinterpret_cast<__half2*>(Ch + (size_t)(r0 + 8) * N + cb) =
                    __floats2half2_rn(v2, v3);
            }
        }
    }
}

// ---------------------------------------------------------------------------
// Sliding-window attention: 256 threads, 2 threads per query (each owns 32 of
// the 64 head dims); one shfl_xor combines the score partials.
// ---------------------------------------------------------------------------
__global__ __launch_bounds__(256, 2)
void attn_kernel(const float* __restrict__ q, const float* __restrict__ k,
                 const float* __restrict__ v, float* __restrict__ out)
{
    extern __shared__ float sma[];
    float* ks = sma;
    float* vs = sma + KT * 64;

    const int c = blockIdx.x, h = blockIdx.y, b = blockIdx.z;
    const int tid = threadIdx.x;
    const int qi = tid >> 1;        // query within chunk
    const int half = tid & 1;       // which 32-dim half
    const int qpos = c * WW + qi;
    const size_t base_bh = (size_t)b * SS * DD + (size_t)h * 64;

    float qreg[32];
    {
        const float* qp = q + base_bh + (size_t)qpos * DD + half * 32;
#pragma unroll
        for (int i = 0; i < 8; i++) {
            float4 t = *reinterpret_cast<const float4*>(qp + i * 4);
            qreg[i * 4 + 0] = t.x; qreg[i * 4 + 1] = t.y;
            qreg[i * 4 + 2] = t.z; qreg[i * 4 + 3] = t.w;
        }
    }

    float o[32];
#pragma unroll
    for (int d = 0; d < 32; d++) o[d] = 0.0f;
    float m = -1e30f, l = 0.0f;

    for (int kt = 0; kt < 2; kt++) {
        for (int idx = tid; idx < KT * 16; idx += 256) {
            int row = idx >> 4;
            int c4  = (idx & 15) << 2;
            int kpos = c * WW - WW + kt * KT + row;
            float4 kv = make_float4(0.f, 0.f, 0.f, 0.f);
            float4 vv = make_float4(0.f, 0.f, 0.f, 0.f);
            if (kpos >= 0 && kpos < SS) {
                size_t off = base_bh + (size_t)kpos * DD + c4;
                kv = *reinterpret_cast<const float4*>(k + off);
                vv = *reinterpret_cast<const float4*>(v + off);
            }
            *reinterpret_cast<float4*>(ks + row * 64 + c4) = kv;
            *reinterpret_cast<float4*>(vs + row * 64 + c4) = vv;
        }
        __syncthreads();

#pragma unroll 1
        for (int j0 = 0; j0 < KT; j0 += 8) {
            float sc[8];
#pragma unroll
            for (int j = 0; j < 8; j++) {
                const float* kr = ks + (j0 + j) * 64 + half * 32;
                float s0 = 0.f, s1 = 0.f, s2 = 0.f, s3 = 0.f;
#pragma unroll
                for (int d = 0; d < 32; d += 4) {
                    s0 = fmaf(qreg[d + 0], kr[d + 0], s0);
                    s1 = fmaf(qreg[d + 1], kr[d + 1], s1);
                    s2 = fmaf(qreg[d + 2], kr[d + 2], s2);
                    s3 = fmaf(qreg[d + 3], kr[d + 3], s3);
                }
                float part = (s0 + s1) + (s2 + s3);
                float s = part + __shfl_xor_sync(0xffffffffu, part, 1);
                int kjw  = kt * KT + j0 + j;
                int kpos = c * WW + kjw - WW;
                bool ok = (kjw >= qi) && (kjw <= qi + 2 * WW) &&
                          (kpos >= 0) && (kpos < SS);
                sc[j] = ok ? s : -3.0e38f;
            }
            float mc = sc[0];
#pragma unroll
            for (int j = 1; j < 8; j++) mc = fmaxf(mc, sc[j]);
            float mn = fmaxf(m, mc);
            float scale = __expf(m - mn);
            float p[8];
            float ls = 0.f;
#pragma unroll
            for (int j = 0; j < 8; j++) { p[j] = __expf(sc[j] - mn); ls += p[j]; }
            l = l * scale + ls;
            m = mn;
#pragma unroll
            for (int d = 0; d < 32; d++) o[d] *= scale;
#pragma unroll
            for (int j = 0; j < 8; j++) {
                const float* vr = vs + (j0 + j) * 64 + half * 32;
                float pj = p[j];
#pragma unroll
                for (int d = 0; d < 32; d++) o[d] = fmaf(pj, vr[d], o[d]);
            }
        }
        __syncthreads();
    }

    float inv = 1.0f / l;
    float* op = out + base_bh + (size_t)qpos * DD + half * 32;
#pragma unroll
    for (int i = 0; i < 8; i++) {
        float4 t;
        t.x = o[i * 4 + 0] * inv; t.y = o[i * 4 + 1] * inv;
        t.z = o[i * 4 + 2] * inv; t.w = o[i * 4 + 3] * inv;
        *reinterpret_cast<float4*>(op + i * 4) = t;
    }
}

// ---------------------------------------------------------------------------
// Residual add + LayerNorm; writes fp32 out and fp16 twin.
// ---------------------------------------------------------------------------
__device__ __forceinline__ float block_sum(float v, float* sh)
{
    __syncthreads();
    int lane = threadIdx.x & 31, w = threadIdx.x >> 5;
#pragma unroll
    for (int o = 16; o; o >>= 1) v += __shfl_xor_sync(0xffffffffu, v, o);
    if (lane == 0) sh[w] = v;
    __syncthreads();
    float t = (lane < 8) ? sh[lane] : 0.0f;
#pragma unroll
    for (int o = 4; o; o >>= 1) t += __shfl_xor_sync(0xffffffffu, t, o);
    if (threadIdx.x == 0) sh[0] = t;
    __syncthreads();
    return sh[0];
}

__global__ __launch_bounds__(256)
void add_ln_kernel(const float* __restrict__ x, const float* __restrict__ r,
                   const float* __restrict__ g, const float* __restrict__ bt,
                   float* __restrict__ out, __half* __restrict__ out16)
{
    __shared__ float sh[8];
    const int row = blockIdx.x;
    const int tid = threadIdx.x;
    const float* xr = x + (size_t)row * DD;
    const float* rr = r + (size_t)row * DD;

    float vals[3];
    float s = 0.f;
#pragma unroll
    for (int i = 0; i < 3; i++) {
        int d = tid + i * 256;
        float v = xr[d] + rr[d];
        vals[i] = v;
        s += v;
    }
    s = block_sum(s, sh);
    float mean = s * (1.0f / (float)DD);
    float vs2 = 0.f;
#pragma unroll
    for (int i = 0; i < 3; i++) {
        float d = vals[i] - mean;
        vs2 += d * d;
    }
    vs2 = block_sum(vs2, sh);
    float inv = rsqrtf(vs2 * (1.0f / (float)DD) + 1e-5f);

    float* orow = out + (size_t)row * DD;
    __half* hrow = out16 + (size_t)row * DD;
#pragma unroll
    for (int i = 0; i < 3; i++) {
        int d = tid + i * 256;
        float v = (vals[i] - mean) * inv * g[d] + bt[d];
        orow[d] = v;
        hrow[d] = __float2half_rn(v);
    }
}

// ---------------------------------------------------------------------------
// Host driver
// ---------------------------------------------------------------------------
extern "C" void kernel_launch(void* const* d_in, const int* in_sizes, int n_in,
                              void* d_out, int out_size)
{
    (void)in_sizes; (void)n_in; (void)out_size;

    const float* x0  = (const float*)d_in[0];
    const float* Wq  = (const float*)d_in[1];
    const float* bq  = (const float*)d_in[2];
    const float* Wk  = (const float*)d_in[3];
    const float* bk  = (const float*)d_in[4];
    const float* Wv  = (const float*)d_in[5];
    const float* bv  = (const float*)d_in[6];
    const float* W1  = (const float*)d_in[7];
    const float* b1  = (const float*)d_in[8];
    const float* W2  = (const float*)d_in[9];
    const float* b2  = (const float*)d_in[10];
    const float* g1  = (const float*)d_in[11];
    const float* be1 = (const float*)d_in[12];
    const float* g2  = (const float*)d_in[13];
    const float* be2 = (const float*)d_in[14];

    float* outp = (float*)d_out;

    float *xb_run, *xbb, *qb, *kb, *vb, *ab;
    __half *xin16, *xb16, *h16, *wqt, *wkt, *wvt, *w1t, *w2t;
    cudaGetSymbolAddress((void**)&xb_run, g_x);
    cudaGetSymbolAddress((void**)&xbb, g_xb);
    cudaGetSymbolAddress((void**)&qb, g_q);
    cudaGetSymbolAddress((void**)&kb, g_k);
    cudaGetSymbolAddress((void**)&vb, g_v);
    cudaGetSymbolAddress((void**)&ab, g_a);
    cudaGetSymbolAddress((void**)&xin16, g_xin16);
    cudaGetSymbolAddress((void**)&xb16, g_xb16);
    cudaGetSymbolAddress((void**)&h16, g_h16);
    cudaGetSymbolAddress((void**)&wqt, g_WqT);
    cudaGetSymbolAddress((void**)&wkt, g_WkT);
    cudaGetSymbolAddress((void**)&wvt, g_WvT);
    cudaGetSymbolAddress((void**)&w1t, g_W1T);
    cudaGetSymbolAddress((void**)&w2t, g_W2T);

    const int attn_smem = 2 * KT * 64 * (int)sizeof(float);  // 96 KB
    cudaFuncSetAttribute(attn_kernel, cudaFuncAttributeMaxDynamicSharedMemorySize,
                         attn_smem);
    const int gemm_smem = 2 * GSTAGES * HSTAGE * (int)sizeof(__half); // 108 KB
    cudaFuncSetAttribute(gemm_f16, cudaFuncAttributeMaxDynamicSharedMemorySize,
                         gemm_smem);

    // Once per replay: weight transposes (fp32 -> fp16 [N,K]) + x0 fp16 twin.
    dim3 tb(32, 8);
    transpose_w<<<dim3(DD / 32, DD / 32, 4), tb>>>(Wq, wqt, DD, DD);
    transpose_w<<<dim3(DD / 32, DD / 32, 4), tb>>>(Wk, wkt, DD, DD);
    transpose_w<<<dim3(DD / 32, DD / 32, 4), tb>>>(Wv, wvt, DD, DD);
    transpose_w<<<dim3(FFD / 32, DD / 32, 4), tb>>>(W1, w1t, DD, FFD);
    transpose_w<<<dim3(DD / 32, FFD / 32, 4), tb>>>(W2, w2t, FFD, DD);
    f2h_kernel<<<(ROWS * DD / 4 + 255) / 256, 256>>>(x0, xin16, ROWS * DD);

    dim3 gD(DD / GBN, ROWS / GBM);    // (6, 128)
    dim3 gF(FFD / GBN, ROWS / GBM);   // (24, 128)
    dim3 gA(NC, HH, BB);

    const float* xc = x0;   // fp32 layer input (residual source)
    for (int l = 0; l < 4; l++) {
        const size_t wOff  = (size_t)l * DD * DD;
        const size_t wfOff = (size_t)l * DD * FFD;

        gemm_f16<<<gD, 256, gemm_smem>>>(xin16, wqt + wOff, bq + l * DD, qb,
                                         (__half*)0, ROWS, DD, DD, 0.125f, 0);
        gemm_f16<<<gD, 256, gemm_smem>>>(xin16, wkt + wOff, bk + l * DD, kb,
                                         (__half*)0, ROWS, DD, DD, 1.0f, 0);
        gemm_f16<<<gD, 256, gemm_smem>>>(xin16, wvt + wOff, bv + l * DD, vb,
                                         (__half*)0, ROWS, DD, DD, 1.0f, 0);

        attn_kernel<<<gA, 256, attn_smem>>>(qb, kb, vb, ab);

        add_ln_kernel<<<ROWS, 256>>>(xc, ab, g1 + l * DD, be1 + l * DD,
                                     xbb, xb16);

        gemm_f16<<<gF, 256, gemm_smem>>>(xb16, w1t + wfOff, b1 + l * FFD,
                                         (float*)0, h16, ROWS, FFD, DD, 1.0f, 1);
        gemm_f16<<<gD, 256, gemm_smem>>>(h16, w2t + wfOff, b2 + l * DD, ab,
                                         (__half*)0, ROWS, DD, FFD, 1.0f, 0);

        float* xdst = (l == 3) ? outp : xb_run;
        add_ln_kernel<<<ROWS, 256>>>(xbb, ab, g2 + l * DD, be2 + l * DD,
                                     xdst, xin16);

        xc = xb_run;
    }
}

// round 5
// speedup vs baseline: 6.0301x; 2.1008x over previous
#include <cuda_runtime.h>
#include <cuda_fp16.h>
#include <math.h>
#include <stdint.h>

#define BB 4
#define SS 4096
#define DD 768
#define FFD 3072
#define HH 12
#define WW 128
#define NC (SS / WW)
#define ROWS (BB * SS)

#define GBM 128
#define GBN 128
#define GBK 32
#define GSTAGES 3
#define HSTRIDE 72                    // halves per smem row (padded)
#define HSTAGE (128 * HSTRIDE)        // halves per tile per stage

// ---------------------------------------------------------------------------
// Scratch (device globals; no runtime allocation allowed)
// ---------------------------------------------------------------------------
__device__ float  g_x[ROWS * DD];          // running x (fp32)
__device__ float  g_xb[ROWS * DD];         // post-LN1 x (fp32)
__device__ float  g_a[ROWS * DD];          // attn out / FF2 out (fp32)
__device__ __half g_xin16[ROWS * DD];      // fp16 twin of layer input
__device__ __half g_xb16[ROWS * DD];       // fp16 twin of post-LN1 x
__device__ __half g_h16[(size_t)ROWS * FFD];   // FF hidden (fp16)
__device__ __half g_qkv16[(size_t)ROWS * 3 * DD]; // fused qkv out (fp16)
__device__ __half g_Wqkv[4 * 3 * DD * DD]; // [L][2304][768] fp16 (q pre-scaled)
__device__ __half g_W1T[4 * DD * FFD];
__device__ __half g_W2T[4 * DD * FFD];
__device__ float  g_bqkv[4 * 3 * DD];      // concat bias (bq pre-scaled)

// ---------------------------------------------------------------------------
// Helpers (family-portable PTX only: cp.async, mma.sync, ldmatrix)
// ---------------------------------------------------------------------------
__device__ __forceinline__ uint32_t smem_u32(const void* p) {
    uint32_t a;
    asm("{ .reg .u64 t; cvta.to.shared.u64 t, %1; cvt.u32.u64 %0, t; }"
        : "=r"(a) : "l"(p));
    return a;
}
__device__ __forceinline__ void cp_async16(uint32_t dst, const void* src) {
    asm volatile("cp.async.cg.shared.global [%0], [%1], 16;"
                 :: "r"(dst), "l"(src));
}
__device__ __forceinline__ void cp_commit() {
    asm volatile("cp.async.commit_group;" ::: "memory");
}
template <int N>
__device__ __forceinline__ void cp_wait() {
    asm volatile("cp.async.wait_group %0;" :: "n"(N) : "memory");
}
__device__ __forceinline__ void mma_f16(float* c, const uint32_t* a,
                                        const uint32_t* b) {
    asm volatile(
        "mma.sync.aligned.m16n8k16.row.col.f32.f16.f16.f32 "
        "{%0,%1,%2,%3}, {%4,%5,%6,%7}, {%8,%9}, {%0,%1,%2,%3};"
        : "+f"(c[0]), "+f"(c[1]), "+f"(c[2]), "+f"(c[3])
        : "r"(a[0]), "r"(a[1]), "r"(a[2]), "r"(a[3]), "r"(b[0]), "r"(b[1]));
}
__device__ __forceinline__ void ldsm_x4(uint32_t* r, uint32_t addr) {
    asm volatile("ldmatrix.sync.aligned.m8n8.x4.shared.b16 {%0,%1,%2,%3}, [%4];"
                 : "=r"(r[0]), "=r"(r[1]), "=r"(r[2]), "=r"(r[3]) : "r"(addr));
}
__device__ __forceinline__ uint32_t h2u(float x, float y) {
    __half2 h = __floats2half2_rn(x, y);
    return *reinterpret_cast<uint32_t*>(&h);
}

// ---------------------------------------------------------------------------
// Weight transpose: src [L, K, N] fp32 -> dst [L(l_stride), N, K] fp16*scale.
// ---------------------------------------------------------------------------
__global__ __launch_bounds__(256)
void transpose_w(const float* __restrict__ src, __half* __restrict__ dst,
                 int K, int N, size_t l_stride, float scale)
{
    __shared__ float t[32][33];
    const int l = blockIdx.z;
    src += (size_t)l * K * N;
    dst += (size_t)l * l_stride;
    const int kb = blockIdx.y * 32, nb = blockIdx.x * 32;
    const int tx = threadIdx.x, ty = threadIdx.y;  // 32 x 8
#pragma unroll
    for (int i = 0; i < 32; i += 8)
        t[ty + i][tx] = src[(size_t)(kb + ty + i) * N + nb + tx];
    __syncthreads();
#pragma unroll
    for (int i = 0; i < 32; i += 8)
        dst[(size_t)(nb + ty + i) * K + kb + tx] =
            __float2half_rn(t[tx][ty + i] * scale);
}

// fp32 -> fp16 convert (for initial x)
__global__ __launch_bounds__(256)
void f2h_kernel(const float* __restrict__ src, __half* __restrict__ dst, int n)
{
    int i = (blockIdx.x * 256 + threadIdx.x) * 4;
    if (i < n) {
        float4 v = *reinterpret_cast<const float4*>(src + i);
        *reinterpret_cast<__half2*>(dst + i) = __floats2half2_rn(v.x, v.y);
        *reinterpret_cast<__half2*>(dst + i + 2) = __floats2half2_rn(v.z, v.w);
    }
}

// concat qkv bias (bq pre-scaled by 0.125)
__global__ __launch_bounds__(256)
void prep_bias(const float* __restrict__ bq, const float* __restrict__ bk,
               const float* __restrict__ bv, float* __restrict__ out)
{
    int i = blockIdx.x * 256 + threadIdx.x;   // 4*2304
    if (i >= 4 * 3 * DD) return;
    int l = i / (3 * DD), r = i % (3 * DD);
    float v;
    if (r < DD) v = bq[l * DD + r] * 0.125f;
    else if (r < 2 * DD) v = bk[l * DD + r - DD];
    else v = bv[l * DD + r - 2 * DD];
    out[i] = v;
}

// ---------------------------------------------------------------------------
// fp16 mma.sync GEMM with ldmatrix fragment loads.
// A: [M,K] fp16 row-major. BT: [N,K] fp16 row-major.
// 128x128 tile, BK=32, 3-stage cp.async, 8 warps (warp tile 32x64).
// ---------------------------------------------------------------------------
__global__ __launch_bounds__(256, 2)
void gemm_f16(const __half* __restrict__ A, const __half* __restrict__ BT,
              const float* __restrict__ bias, float* __restrict__ Cf,
              __half* __restrict__ Ch,
              int M, int N, int K, int relu)
{
    extern __shared__ __half hsm[];
    __half* As = hsm;
    __half* Bs = hsm + GSTAGES * HSTAGE;

    const int tid = threadIdx.x;
    const int wid = tid >> 5, lane = tid & 31;
    const int warp_m = wid >> 1;     // 0..3
    const int warp_n = wid & 1;      // 0..1
    const int g = lane >> 2;
    const int t4 = lane & 3;

    const int brow = blockIdx.y, bcol = blockIdx.x;
    const __half* Abase = A + (size_t)brow * GBM * K;
    const __half* Bbase = BT + (size_t)bcol * GBN * K;

    const uint32_t AsU = smem_u32(As);
    const uint32_t BsU = smem_u32(Bs);

    const int nk = K / GBK;

    auto stage = [&](int s) {
        const int k0 = s * GBK;
        const uint32_t off = (uint32_t)((s % GSTAGES) * HSTAGE) * 2u;
#pragma unroll
        for (int i = 0; i < 2; i++) {
            int id = tid + i * 256;
            int r = id >> 2, c4 = id & 3;
            cp_async16(AsU + off + (uint32_t)(r * HSTRIDE + c4 * 8) * 2u,
                       Abase + (size_t)r * K + k0 + c4 * 8);
        }
#pragma unroll
        for (int i = 0; i < 2; i++) {
            int id = tid + i * 256;
            int r = id >> 2, c4 = id & 3;
            cp_async16(BsU + off + (uint32_t)(r * HSTRIDE + c4 * 8) * 2u,
                       Bbase + (size_t)r * K + k0 + c4 * 8);
        }
        cp_commit();
    };

    float acc[2][8][4];
#pragma unroll
    for (int mt = 0; mt < 2; mt++)
#pragma unroll
        for (int nt = 0; nt < 8; nt++)
#pragma unroll
            for (int j = 0; j < 4; j++) acc[mt][nt][j] = 0.0f;

#pragma unroll
    for (int s = 0; s < GSTAGES - 1; s++) {
        if (s < nk) stage(s); else cp_commit();
    }

    const uint32_t lrow = (uint32_t)(lane & 15) * (HSTRIDE * 2);
    const uint32_t lcol = (uint32_t)(lane >> 4) * 16;

    for (int ks = 0; ks < nk; ks++) {
        cp_wait<GSTAGES - 2>();
        __syncthreads();

        if (ks + GSTAGES - 1 < nk) stage(ks + GSTAGES - 1); else cp_commit();

        const uint32_t abuf = AsU + (uint32_t)((ks % GSTAGES) * HSTAGE) * 2u;
        const uint32_t bbuf = BsU + (uint32_t)((ks % GSTAGES) * HSTAGE) * 2u;

#pragma unroll
        for (int kk = 0; kk < 2; kk++) {
            const uint32_t co = (uint32_t)kk * 32 + lcol;
            uint32_t a[2][4];
#pragma unroll
            for (int mt = 0; mt < 2; mt++)
                ldsm_x4(a[mt], abuf + (uint32_t)(warp_m * 32 + mt * 16) *
                                       (HSTRIDE * 2) + lrow + co);
            uint32_t b[8][2];
#pragma unroll
            for (int np = 0; np < 4; np++) {
                uint32_t tr[4];
                ldsm_x4(tr, bbuf + (uint32_t)(warp_n * 64 + np * 16) *
                                    (HSTRIDE * 2) + lrow + co);
                b[np * 2][0] = tr[0]; b[np * 2 + 1][0] = tr[1];
                b[np * 2][1] = tr[2]; b[np * 2 + 1][1] = tr[3];
            }
#pragma unroll
            for (int mt = 0; mt < 2; mt++)
#pragma unroll
                for (int nt = 0; nt < 8; nt++)
                    mma_f16(acc[mt][nt], a[mt], b[nt]);
        }
        __syncthreads();
    }

    // epilogue
#pragma unroll
    for (int mt = 0; mt < 2; mt++) {
        const int r0 = brow * GBM + warp_m * 32 + mt * 16 + g;
#pragma unroll
        for (int nt = 0; nt < 8; nt++) {
            const int cb = bcol * GBN + warp_n * 64 + nt * 8 + t4 * 2;
            const float b0 = bias[cb], b1 = bias[cb + 1];
            float v0 = acc[mt][nt][0] + b0;
            float v1 = acc[mt][nt][1] + b1;
            float v2 = acc[mt][nt][2] + b0;
            float v3 = acc[mt][nt][3] + b1;
            if (relu) {
                v0 = fmaxf(v0, 0.f); v1 = fmaxf(v1, 0.f);
                v2 = fmaxf(v2, 0.f); v3 = fmaxf(v3, 0.f);
            }
            if (Cf) {
                *reinterpret_cast<float2*>(Cf + (size_t)r0 * N + cb) =
                    make_float2(v0, v1);
                *reinterpret_cast<float2*>(Cf + (size_t)(r0 + 8) * N + cb) =
                    make_float2(v2, v3);
            }
            if (Ch) {
                *reinterpret_cast<__half2*>(Ch + (size_t)r0 * N + cb) =
                    __floats2half2_rn(v0, v1);
                *reinterpret_cast<__half2*>(Ch + (size_t)(r0 + 8) * N + cb) =
                    __floats2half2_rn(v2, v3);
            }
        }
    }
}

// ---------------------------------------------------------------------------
// Flash sliding-window attention with mma.sync.
// Grid (NC, HH, BB), 256 threads = 8 warps x 16 queries.
// qkv: [ROWS][2304] fp16 (q cols 0-767 pre-scaled, k 768-1535, v 1536-2303).
// ---------------------------------------------------------------------------
#define QS_OFF 0
#define KS_OFF (128 * HSTRIDE)                  // 9216 halves
#define VT_OFF (KS_OFF + 192 * HSTRIDE)         // +13824 halves
#define VT_STRIDE 202
#define ATTN_SMEM ((VT_OFF + 64 * VT_STRIDE) * 2)

__global__ __launch_bounds__(256, 2)
void attn_mma(const __half* __restrict__ qkv, float* __restrict__ out)
{
    extern __shared__ __half ash[];
    __half* Ks = ash + KS_OFF;
    __half* VT = ash + VT_OFF;

    const int c = blockIdx.x, h = blockIdx.y, b = blockIdx.z;
    const int tid = threadIdx.x;
    const int w = tid >> 5, lane = tid & 31;
    const int g = lane >> 2, t4 = lane & 3;
    const int qoff = h * 64, koff = DD + h * 64, voff = 2 * DD + h * 64;
    const int cbase = c * 128 - 128;

    const uint32_t QsU = smem_u32(ash);
    const uint32_t KsU = smem_u32(Ks);

    // stage Q (128 rows x 64 halves)
#pragma unroll
    for (int i = 0; i < 4; i++) {
        int id = tid + i * 256;
        int r = id >> 3, ch = id & 7;
        uint4 v = *reinterpret_cast<const uint4*>(
            qkv + (size_t)(b * SS + c * 128 + r) * (3 * DD) + qoff + ch * 8);
        *reinterpret_cast<uint4*>(&ash[r * HSTRIDE + ch * 8]) = v;
    }
    __syncthreads();

    // Q fragments (held for whole kernel)
    const uint32_t lrow = (uint32_t)(lane & 15) * (HSTRIDE * 2);
    const uint32_t lcol = (uint32_t)(lane >> 4) * 16;
    uint32_t qa[4][4];
#pragma unroll
    for (int ks = 0; ks < 4; ks++)
        ldsm_x4(qa[ks], QsU + (uint32_t)(w * 16) * (HSTRIDE * 2) + lrow +
                        (uint32_t)ks * 32 + lcol);

    float o[8][4];
#pragma unroll
    for (int ch = 0; ch < 8; ch++)
#pragma unroll
        for (int j = 0; j < 4; j++) o[ch][j] = 0.0f;
    float m0 = -1e30f, m1 = -1e30f, l0 = 0.0f, l1 = 0.0f;
    const int qi0 = w * 16 + g, qi1 = qi0 + 8;

    for (int t = 0; t < 2; t++) {
        __syncthreads();
        const int kw0 = t * 192;
        // stage K [192][HSTRIDE] and V transposed [64][VT_STRIDE]
#pragma unroll
        for (int i = 0; i < 6; i++) {
            int id = tid + i * 256;
            int r = id >> 3, ch = id & 7;
            int kpos = cbase + kw0 + r;
            uint4 kv = make_uint4(0, 0, 0, 0), vv = make_uint4(0, 0, 0, 0);
            if (kpos >= 0 && kpos < SS) {
                const __half* rp = qkv + (size_t)(b * SS + kpos) * (3 * DD);
                kv = *reinterpret_cast<const uint4*>(rp + koff + ch * 8);
                vv = *reinterpret_cast<const uint4*>(rp + voff + ch * 8);
            }
            *reinterpret_cast<uint4*>(&Ks[r * HSTRIDE + ch * 8]) = kv;
            const __half* vh = reinterpret_cast<const __half*>(&vv);
#pragma unroll
            for (int d8 = 0; d8 < 8; d8++)
                VT[(ch * 8 + d8) * VT_STRIDE + r] = vh[d8];
        }
        __syncthreads();

        const int jb_lo = (t == 0) ? w : 12;
        const int jb_hi = (t == 0) ? 11 : (w + 16);

        for (int jb = jb_lo; jb <= jb_hi; jb++) {
            const int j0 = jb * 16 - kw0;
            // S = Q K^T for 16 keys (two n8 chunks)
            float s0[4] = {0.f, 0.f, 0.f, 0.f};
            float s1[4] = {0.f, 0.f, 0.f, 0.f};
#pragma unroll
            for (int ks = 0; ks < 4; ks++) {
                uint32_t kb[4];
                ldsm_x4(kb, KsU + (uint32_t)j0 * (HSTRIDE * 2) + lrow +
                            (uint32_t)ks * 32 + lcol);
                uint32_t b0[2] = {kb[0], kb[2]};
                uint32_t b1[2] = {kb[1], kb[3]};
                mma_f16(s0, qa[ks], b0);
                mma_f16(s1, qa[ks], b1);
            }
            // mask
            const int cw = jb * 16 + 2 * t4;
            {
                auto mk = [&](float s, int cwi, int qi) -> float {
                    unsigned d = (unsigned)(cwi - qi);
                    int kp = cbase + cwi;
                    return (d <= 256u && kp >= 0 && kp < SS) ? s : -3.0e38f;
                };
                s0[0] = mk(s0[0], cw,     qi0); s0[1] = mk(s0[1], cw + 1, qi0);
                s0[2] = mk(s0[2], cw,     qi1); s0[3] = mk(s0[3], cw + 1, qi1);
                s1[0] = mk(s1[0], cw + 8, qi0); s1[1] = mk(s1[1], cw + 9, qi0);
                s1[2] = mk(s1[2], cw + 8, qi1); s1[3] = mk(s1[3], cw + 9, qi1);
            }
            // online softmax
            float bm0 = fmaxf(fmaxf(s0[0], s0[1]), fmaxf(s1[0], s1[1]));
            float bm1 = fmaxf(fmaxf(s0[2], s0[3]), fmaxf(s1[2], s1[3]));
            bm0 = fmaxf(bm0, __shfl_xor_sync(0xffffffffu, bm0, 1));
            bm0 = fmaxf(bm0, __shfl_xor_sync(0xffffffffu, bm0, 2));
            bm1 = fmaxf(bm1, __shfl_xor_sync(0xffffffffu, bm1, 1));
            bm1 = fmaxf(bm1, __shfl_xor_sync(0xffffffffu, bm1, 2));
            float mn0 = fmaxf(m0, bm0), mn1 = fmaxf(m1, bm1);
            float sc0 = __expf(m0 - mn0), sc1 = __expf(m1 - mn1);
            m0 = mn0; m1 = mn1;
            float p00 = __expf(s0[0] - mn0), p01 = __expf(s0[1] - mn0);
            float p10 = __expf(s0[2] - mn1), p11 = __expf(s0[3] - mn1);
            float p02 = __expf(s1[0] - mn0), p03 = __expf(s1[1] - mn0);
            float p12 = __expf(s1[2] - mn1), p13 = __expf(s1[3] - mn1);
            float rs0 = (p00 + p01) + (p02 + p03);
            float rs1 = (p10 + p11) + (p12 + p13);
            rs0 += __shfl_xor_sync(0xffffffffu, rs0, 1);
            rs0 += __shfl_xor_sync(0xffffffffu, rs0, 2);
            rs1 += __shfl_xor_sync(0xffffffffu, rs1, 1);
            rs1 += __shfl_xor_sync(0xffffffffu, rs1, 2);
            l0 = l0 * sc0 + rs0;
            l1 = l1 * sc1 + rs1;

            uint32_t pa[4];
            pa[0] = h2u(p00, p01);
            pa[1] = h2u(p10, p11);
            pa[2] = h2u(p02, p03);
            pa[3] = h2u(p12, p13);

            // rescale O and accumulate P V
#pragma unroll
            for (int ch = 0; ch < 8; ch++) {
                o[ch][0] *= sc0; o[ch][1] *= sc0;
                o[ch][2] *= sc1; o[ch][3] *= sc1;
                const __half* vp = &VT[(ch * 8 + g) * VT_STRIDE + j0 + 2 * t4];
                uint32_t bb[2];
                bb[0] = *reinterpret_cast<const uint32_t*>(vp);
                bb[1] = *reinterpret_cast<const uint32_t*>(vp + 8);
                mma_f16(o[ch], pa, bb);
            }
        }
    }

    const float inv0 = 1.0f / l0, inv1 = 1.0f / l1;
    float* op0 = out + (size_t)(b * SS + c * 128 + w * 16 + g) * DD + h * 64;
    float* op1 = op0 + 8 * DD;
#pragma unroll
    for (int ch = 0; ch < 8; ch++) {
        *reinterpret_cast<float2*>(op0 + ch * 8 + 2 * t4) =
            make_float2(o[ch][0] * inv0, o[ch][1] * inv0);
        *reinterpret_cast<float2*>(op1 + ch * 8 + 2 * t4) =
            make_float2(o[ch][2] * inv1, o[ch][3] * inv1);
    }
}

// ---------------------------------------------------------------------------
// Residual add + LayerNorm; writes fp32 out and fp16 twin.
// ---------------------------------------------------------------------------
__device__ __forceinline__ float block_sum(float v, float* sh)
{
    __syncthreads();
    int lane = threadIdx.x & 31, w = threadIdx.x >> 5;
#pragma unroll
    for (int o = 16; o; o >>= 1) v += __shfl_xor_sync(0xffffffffu, v, o);
    if (lane == 0) sh[w] = v;
    __syncthreads();
    float t = (lane < 8) ? sh[lane] : 0.0f;
#pragma unroll
    for (int o = 4; o; o >>= 1) t += __shfl_xor_sync(0xffffffffu, t, o);
    if (threadIdx.x == 0) sh[0] = t;
    __syncthreads();
    return sh[0];
}

__global__ __launch_bounds__(256)
void add_ln_kernel(const float* __restrict__ x, const float* __restrict__ r,
                   const float* __restrict__ g, const float* __restrict__ bt,
                   float* __restrict__ out, __half* __restrict__ out16)
{
    __shared__ float sh[8];
    const int row = blockIdx.x;
    const int tid = threadIdx.x;
    const float* xr = x + (size_t)row * DD;
    const float* rr = r + (size_t)row * DD;

    float vals[3];
    float s = 0.f;
#pragma unroll
    for (int i = 0; i < 3; i++) {
        int d = tid + i * 256;
        float v = xr[d] + rr[d];
        vals[i] = v;
        s += v;
    }
    s = block_sum(s, sh);
    float mean = s * (1.0f / (float)DD);
    float vs2 = 0.f;
#pragma unroll
    for (int i = 0; i < 3; i++) {
        float d = vals[i] - mean;
        vs2 += d * d;
    }
    vs2 = block_sum(vs2, sh);
    float inv = rsqrtf(vs2 * (1.0f / (float)DD) + 1e-5f);

    float* orow = out + (size_t)row * DD;
    __half* hrow = out16 + (size_t)row * DD;
#pragma unroll
    for (int i = 0; i < 3; i++) {
        int d = tid + i * 256;
        float v = (vals[i] - mean) * inv * g[d] + bt[d];
        orow[d] = v;
        hrow[d] = __float2half_rn(v);
    }
}

// ---------------------------------------------------------------------------
// Host driver
// ---------------------------------------------------------------------------
extern "C" void kernel_launch(void* const* d_in, const int* in_sizes, int n_in,
                              void* d_out, int out_size)
{
    (void)in_sizes; (void)n_in; (void)out_size;

    const float* x0  = (const float*)d_in[0];
    const float* Wq  = (const float*)d_in[1];
    const float* bq  = (const float*)d_in[2];
    const float* Wk  = (const float*)d_in[3];
    const float* bk  = (const float*)d_in[4];
    const float* Wv  = (const float*)d_in[5];
    const float* bv  = (const float*)d_in[6];
    const float* W1  = (const float*)d_in[7];
    const float* b1  = (const float*)d_in[8];
    const float* W2  = (const float*)d_in[9];
    const float* b2  = (const float*)d_in[10];
    const float* g1  = (const float*)d_in[11];
    const float* be1 = (const float*)d_in[12];
    const float* g2  = (const float*)d_in[13];
    const float* be2 = (const float*)d_in[14];

    float* outp = (float*)d_out;

    float *xb_run, *xbb, *ab, *bqkv;
    __half *xin16, *xb16, *h16, *qkv16, *wqkv, *w1t, *w2t;
    cudaGetSymbolAddress((void**)&xb_run, g_x);
    cudaGetSymbolAddress((void**)&xbb, g_xb);
    cudaGetSymbolAddress((void**)&ab, g_a);
    cudaGetSymbolAddress((void**)&bqkv, g_bqkv);
    cudaGetSymbolAddress((void**)&xin16, g_xin16);
    cudaGetSymbolAddress((void**)&xb16, g_xb16);
    cudaGetSymbolAddress((void**)&h16, g_h16);
    cudaGetSymbolAddress((void**)&qkv16, g_qkv16);
    cudaGetSymbolAddress((void**)&wqkv, g_Wqkv);
    cudaGetSymbolAddress((void**)&w1t, g_W1T);
    cudaGetSymbolAddress((void**)&w2t, g_W2T);

    cudaFuncSetAttribute(attn_mma, cudaFuncAttributeMaxDynamicSharedMemorySize,
                         ATTN_SMEM);
    const int gemm_smem = 2 * GSTAGES * HSTAGE * (int)sizeof(__half);
    cudaFuncSetAttribute(gemm_f16, cudaFuncAttributeMaxDynamicSharedMemorySize,
                         gemm_smem);

    // Prep: weight transposes into fused/split fp16 buffers + bias + x0 fp16.
    dim3 tb(32, 8);
    const size_t qkvL = (size_t)3 * DD * DD;
    transpose_w<<<dim3(DD / 32, DD / 32, 4), tb>>>(Wq, wqkv, DD, DD, qkvL, 0.125f);
    transpose_w<<<dim3(DD / 32, DD / 32, 4), tb>>>(Wk, wqkv + (size_t)DD * DD,
                                                   DD, DD, qkvL, 1.0f);
    transpose_w<<<dim3(DD / 32, DD / 32, 4), tb>>>(Wv, wqkv + (size_t)2 * DD * DD,
                                                   DD, DD, qkvL, 1.0f);
    transpose_w<<<dim3(FFD / 32, DD / 32, 4), tb>>>(W1, w1t, DD, FFD,
                                                    (size_t)DD * FFD, 1.0f);
    transpose_w<<<dim3(DD / 32, FFD / 32, 4), tb>>>(W2, w2t, FFD, DD,
                                                    (size_t)DD * FFD, 1.0f);
    prep_bias<<<(4 * 3 * DD + 255) / 256, 256>>>(bq, bk, bv, bqkv);
    f2h_kernel<<<(ROWS * DD / 4 + 255) / 256, 256>>>(x0, xin16, ROWS * DD);

    dim3 gQKV(3 * DD / GBN, ROWS / GBM);   // (18, 128)
    dim3 gD(DD / GBN, ROWS / GBM);         // (6, 128)
    dim3 gF(FFD / GBN, ROWS / GBM);        // (24, 128)
    dim3 gA(NC, HH, BB);

    const float* xc = x0;
    for (int l = 0; l < 4; l++) {
        gemm_f16<<<gQKV, 256, gemm_smem>>>(xin16, wqkv + l * qkvL,
                                           bqkv + l * 3 * DD,
                                           (float*)0, qkv16,
                                           ROWS, 3 * DD, DD, 0);

        attn_mma<<<gA, 256, ATTN_SMEM>>>(qkv16, ab);

        add_ln_kernel<<<ROWS, 256>>>(xc, ab, g1 + l * DD, be1 + l * DD,
                                     xbb, xb16);

        gemm_f16<<<gF, 256, gemm_smem>>>(xb16, w1t + (size_t)l * DD * FFD,
                                         b1 + l * FFD, (float*)0, h16,
                                         ROWS, FFD, DD, 1);
        gemm_f16<<<gD, 256, gemm_smem>>>(h16, w2t + (size_t)l * DD * FFD,
                                         b2 + l * DD, ab, (__half*)0,
                                         ROWS, DD, FFD, 0);

        float* xdst = (l == 3) ? outp : xb_run;
        add_ln_kernel<<<ROWS, 256>>>(xbb, ab, g2 + l * DD, be2 + l * DD,
                                     xdst, xin16);

        xc = xb_run;
    }
}